// round 1
// baseline (speedup 1.0000x reference)
#include <cuda_runtime.h>
#include <cuda_bf16.h>
#include <math.h>

#define NN 20000
#define BB 128
#define KK 20
#define EE 640000
#define NB (NN * BB)          // 2,560,000 floats per T_k
#define NCHUNK 625
#define CHUNK 32              // 625 * 32 = 20000 rows

// -------- static device scratch (no runtime allocation allowed) ----------
__device__ float g_T[(size_t)KK * NN * BB];     // 204.8 MB: T_0..T_19, [k][n][b]
__device__ int   g_deg[NN + 1];
__device__ int   g_rowptr[NN + 1];
__device__ int   g_cursor[NN];
__device__ int   g_ccol[EE];
__device__ float g_cval[EE];
__device__ float g_partial[(size_t)NCHUNK * BB * 10];

// ---------------------------- CSR build ---------------------------------
__global__ void zero_deg_kernel() {
    int i = blockIdx.x * blockDim.x + threadIdx.x;
    if (i <= NN) g_deg[i] = 0;
}

__global__ void degree_kernel(const int* __restrict__ rows) {
    int e = blockIdx.x * blockDim.x + threadIdx.x;
    if (e < EE) atomicAdd(&g_deg[rows[e]], 1);
}

// single-CTA exclusive scan of g_deg -> g_rowptr (also seeds g_cursor)
__global__ void scan_kernel() {
    __shared__ int ssum[1024];
    const int IT = 20;                 // 1024*20 = 20480 >= 20001
    int t = threadIdx.x;
    int base = t * IT;
    int loc[IT];
    int s = 0;
#pragma unroll
    for (int i = 0; i < IT; i++) {
        int idx = base + i;
        int v = (idx < NN) ? g_deg[idx] : 0;
        loc[i] = s;
        s += v;
    }
    ssum[t] = s;
    __syncthreads();
    for (int off = 1; off < 1024; off <<= 1) {
        int v = 0;
        if (t >= off) v = ssum[t - off];
        __syncthreads();
        if (t >= off) ssum[t] += v;
        __syncthreads();
    }
    int pre = (t > 0) ? ssum[t - 1] : 0;
#pragma unroll
    for (int i = 0; i < IT; i++) {
        int idx = base + i;
        if (idx <= NN) {
            int p = pre + loc[i];
            g_rowptr[idx] = p;
            if (idx < NN) g_cursor[idx] = p;
        }
    }
}

__global__ void scatter_kernel(const int* __restrict__ rows,
                               const int* __restrict__ cols,
                               const float* __restrict__ vals) {
    int e = blockIdx.x * blockDim.x + threadIdx.x;
    if (e < EE) {
        int p = atomicAdd(&g_cursor[rows[e]], 1);
        g_ccol[p] = cols[e];
        g_cval[p] = vals[e];
    }
}

// ---------------------- T0 = x^T  ([B,N] -> [N,B]) -----------------------
__global__ void transpose_kernel(const float* __restrict__ x) {
    __shared__ float tile[32][33];
    int n0 = blockIdx.x * 32, b0 = blockIdx.y * 32;
    int tn = n0 + threadIdx.x;
    int tb = b0 + threadIdx.y;          // always < 128
    if (tn < NN) tile[threadIdx.y][threadIdx.x] = x[(size_t)tb * NN + tn];
    __syncthreads();
    int on = n0 + threadIdx.y;
    int ob = b0 + threadIdx.x;
    if (on < NN) g_T[(size_t)on * BB + ob] = tile[threadIdx.x][threadIdx.y];
}

// -------------------- fused Chebyshev SpMM step --------------------------
// T_out[n,:] = alpha * sum_e val_e * T_in[col_e,:]  + beta * T_in2[n,:]
// warp per row, lane covers 4 batch elements (float4)
__global__ void __launch_bounds__(256) spmm_kernel(int kin, int kin2, int kout,
                                                   float alpha, float beta) {
    int gw = (blockIdx.x * blockDim.x + threadIdx.x) >> 5;
    int lane = threadIdx.x & 31;
    if (gw >= NN) return;

    const float4* __restrict__ Tin = (const float4*)(g_T + (size_t)kin * NB);
    float4* __restrict__ Tout = (float4*)(g_T + (size_t)kout * NB);

    int s = g_rowptr[gw];
    int e = g_rowptr[gw + 1];

    float ax = 0.f, ay = 0.f, az = 0.f, aw = 0.f;
    int j = s;
    for (; j + 4 <= e; j += 4) {
        int c0 = g_ccol[j], c1 = g_ccol[j + 1], c2 = g_ccol[j + 2], c3 = g_ccol[j + 3];
        float v0 = g_cval[j], v1 = g_cval[j + 1], v2 = g_cval[j + 2], v3 = g_cval[j + 3];
        float4 g0 = Tin[(size_t)c0 * 32 + lane];
        float4 g1 = Tin[(size_t)c1 * 32 + lane];
        float4 g2 = Tin[(size_t)c2 * 32 + lane];
        float4 g3 = Tin[(size_t)c3 * 32 + lane];
        ax += v0 * g0.x; ay += v0 * g0.y; az += v0 * g0.z; aw += v0 * g0.w;
        ax += v1 * g1.x; ay += v1 * g1.y; az += v1 * g1.z; aw += v1 * g1.w;
        ax += v2 * g2.x; ay += v2 * g2.y; az += v2 * g2.z; aw += v2 * g2.w;
        ax += v3 * g3.x; ay += v3 * g3.y; az += v3 * g3.z; aw += v3 * g3.w;
    }
    for (; j < e; j++) {
        int c = g_ccol[j];
        float v = g_cval[j];
        float4 g = Tin[(size_t)c * 32 + lane];
        ax += v * g.x; ay += v * g.y; az += v * g.z; aw += v * g.w;
    }

    float4 o;
    if (beta != 0.f) {
        const float4* __restrict__ Tp = (const float4*)(g_T + (size_t)kin2 * NB);
        float4 p = Tp[(size_t)gw * 32 + lane];
        o.x = alpha * ax + beta * p.x;
        o.y = alpha * ay + beta * p.y;
        o.z = alpha * az + beta * p.z;
        o.w = alpha * aw + beta * p.w;
    } else {
        o.x = ax; o.y = ay; o.z = az; o.w = aw;   // alpha == 1 for T1
    }
    Tout[(size_t)gw * 32 + lane] = o;
}

// --------- fused epilogue: gc einsum + relu + FC partial sums ------------
// grid = NCHUNK blocks of 128 threads; thread t owns batch b = t for this
// block's 32 rows. partial[chunk][b][j] = sum over those rows.
__global__ void __launch_bounds__(128) final_kernel(const float* __restrict__ Wgc,
                                                    const float* __restrict__ bgc,
                                                    const float* __restrict__ Wfc) {
    __shared__ float sW[KK * 12];   // padded to 12 floats/row for float4 LDS
    __shared__ float sb[10];
    int t = threadIdx.x;
    for (int i = t; i < KK * 12; i += 128) sW[i] = 0.f;
    __syncthreads();
    for (int i = t; i < KK * 10; i += 128) {
        int k = i / 10, f = i % 10;
        sW[k * 12 + f] = Wgc[i];
    }
    if (t < 10) sb[t] = bgc[t];
    __syncthreads();

    const float4* sW4 = (const float4*)sW;
    int b = t;

    float h[10];
#pragma unroll
    for (int j = 0; j < 10; j++) h[j] = 0.f;

    int n0 = blockIdx.x * CHUNK;
    for (int n = n0; n < n0 + CHUNK; n++) {
        float gc[10];
#pragma unroll
        for (int f = 0; f < 10; f++) gc[f] = sb[f];
#pragma unroll
        for (int k = 0; k < KK; k++) {
            float tk = g_T[(size_t)k * NB + (size_t)n * BB + b];
            float4 wA = sW4[k * 3 + 0];
            float4 wB = sW4[k * 3 + 1];
            float4 wC = sW4[k * 3 + 2];
            gc[0] += tk * wA.x; gc[1] += tk * wA.y; gc[2] += tk * wA.z; gc[3] += tk * wA.w;
            gc[4] += tk * wB.x; gc[5] += tk * wB.y; gc[6] += tk * wB.z; gc[7] += tk * wB.w;
            gc[8] += tk * wC.x; gc[9] += tk * wC.y;
        }
#pragma unroll
        for (int f = 0; f < 10; f++) gc[f] = fmaxf(gc[f], 0.f);

        const float4* __restrict__ w4 = (const float4*)(Wfc + (size_t)n * 100);
#pragma unroll
        for (int q = 0; q < 25; q++) {
            float4 wv = w4[q];
            h[(4 * q + 0) % 10] += gc[(4 * q + 0) / 10] * wv.x;
            h[(4 * q + 1) % 10] += gc[(4 * q + 1) / 10] * wv.y;
            h[(4 * q + 2) % 10] += gc[(4 * q + 2) / 10] * wv.z;
            h[(4 * q + 3) % 10] += gc[(4 * q + 3) / 10] * wv.w;
        }
    }

    float* out = g_partial + (size_t)blockIdx.x * BB * 10 + (size_t)b * 10;
#pragma unroll
    for (int j = 0; j < 10; j++) out[j] = h[j];
}

// ------------- deterministic chunk reduction + bias/relu/softmax ---------
__global__ void reduce_softmax_kernel(const float* __restrict__ bfc,
                                      float* __restrict__ out) {
    int b = threadIdx.x;   // 128 threads
    float h[10];
#pragma unroll
    for (int j = 0; j < 10; j++) h[j] = 0.f;
    for (int c = 0; c < NCHUNK; c++) {
        const float* p = g_partial + (size_t)c * BB * 10 + (size_t)b * 10;
#pragma unroll
        for (int j = 0; j < 10; j++) h[j] += p[j];
    }
#pragma unroll
    for (int j = 0; j < 10; j++) h[j] = fmaxf(h[j] + bfc[j], 0.f);
    float m = h[0];
#pragma unroll
    for (int j = 1; j < 10; j++) m = fmaxf(m, h[j]);
    float ex[10];
    float s = 0.f;
#pragma unroll
    for (int j = 0; j < 10; j++) { ex[j] = expf(h[j] - m); s += ex[j]; }
    float inv = 1.f / s;
#pragma unroll
    for (int j = 0; j < 10; j++) out[(size_t)b * 10 + j] = ex[j] * inv;
}

// ------------------------------- launch ----------------------------------
extern "C" void kernel_launch(void* const* d_in, const int* in_sizes, int n_in,
                              void* d_out, int out_size) {
    const float* x    = (const float*)d_in[0];
    const int*   rows = (const int*)d_in[1];
    const int*   cols = (const int*)d_in[2];
    const float* vals = (const float*)d_in[3];
    const float* Wgc  = (const float*)d_in[4];
    const float* bgc  = (const float*)d_in[5];
    const float* Wfc  = (const float*)d_in[6];
    const float* bfc  = (const float*)d_in[7];
    float* out = (float*)d_out;

    // CSR build (replayed per graph launch; deterministic structure, order
    // within a row is atomic-raced but only permutes a float sum)
    zero_deg_kernel<<<(NN + 256) / 256, 256>>>();
    degree_kernel<<<(EE + 255) / 256, 256>>>(rows);
    scan_kernel<<<1, 1024>>>();
    scatter_kernel<<<(EE + 255) / 256, 256>>>(rows, cols, vals);

    // T0 = x^T
    dim3 tb(32, 32), tg((NN + 31) / 32, (BB + 31) / 32);
    transpose_kernel<<<tg, tb>>>(x);

    // Chebyshev chain: T1 = L T0 ; T_k = 2 L T_{k-1} - T_{k-2}
    const int SPMM_GRID = (NN * 32 + 255) / 256;   // warp per row
    spmm_kernel<<<SPMM_GRID, 256>>>(0, 0, 1, 1.0f, 0.0f);
    for (int k = 2; k < KK; k++)
        spmm_kernel<<<SPMM_GRID, 256>>>(k - 1, k - 2, k, 2.0f, -1.0f);

    // fused epilogue + deterministic reduce + softmax
    final_kernel<<<NCHUNK, 128>>>(Wgc, bgc, Wfc);
    reduce_softmax_kernel<<<1, 128>>>(bfc, out);
}

// round 2
// speedup vs baseline: 1.1125x; 1.1125x over previous
#include <cuda_runtime.h>
#include <cuda_fp16.h>
#include <cuda_bf16.h>
#include <math.h>

#define NN 20000
#define BB 128
#define KK 20
#define EE 640000
#define NB (NN * BB)          // 2,560,000 floats per T_k plane
#define NCHUNK 625
#define CHUNK 32              // 625 * 32 = 20000 rows

// -------- static device scratch (no runtime allocation allowed) ----------
__device__ float g_T[(size_t)KK * NN * BB];     // 204.8 MB fp32 masters
__device__ uint2 g_Th[2 * (size_t)NN * 32];     // 10.2 MB: fp16 ping-pong gather copies
__device__ int   g_deg[NN + 1];
__device__ int   g_rowptr[NN + 1];
__device__ int   g_cursor[NN];
__device__ int2  g_pack[EE];                    // packed {col, val bits}
__device__ float g_partial[(size_t)NCHUNK * BB * 10];

// ---------------------------- CSR build ---------------------------------
__global__ void zero_deg_kernel() {
    int i = blockIdx.x * blockDim.x + threadIdx.x;
    if (i <= NN) g_deg[i] = 0;
}

__global__ void degree_kernel(const int* __restrict__ rows) {
    int e = blockIdx.x * blockDim.x + threadIdx.x;
    if (e < EE) atomicAdd(&g_deg[rows[e]], 1);
}

// single-CTA exclusive scan of g_deg -> g_rowptr (also seeds g_cursor)
__global__ void scan_kernel() {
    __shared__ int ssum[1024];
    const int IT = 20;                 // 1024*20 = 20480 >= 20001
    int t = threadIdx.x;
    int base = t * IT;
    int loc[IT];
    int s = 0;
#pragma unroll
    for (int i = 0; i < IT; i++) {
        int idx = base + i;
        int v = (idx < NN) ? g_deg[idx] : 0;
        loc[i] = s;
        s += v;
    }
    ssum[t] = s;
    __syncthreads();
    for (int off = 1; off < 1024; off <<= 1) {
        int v = 0;
        if (t >= off) v = ssum[t - off];
        __syncthreads();
        if (t >= off) ssum[t] += v;
        __syncthreads();
    }
    int pre = (t > 0) ? ssum[t - 1] : 0;
#pragma unroll
    for (int i = 0; i < IT; i++) {
        int idx = base + i;
        if (idx <= NN) {
            int p = pre + loc[i];
            g_rowptr[idx] = p;
            if (idx < NN) g_cursor[idx] = p;
        }
    }
}

__global__ void scatter_kernel(const int* __restrict__ rows,
                               const int* __restrict__ cols,
                               const float* __restrict__ vals) {
    int e = blockIdx.x * blockDim.x + threadIdx.x;
    if (e < EE) {
        int p = atomicAdd(&g_cursor[rows[e]], 1);
        int2 pk;
        pk.x = cols[e];
        pk.y = __float_as_int(vals[e]);
        g_pack[p] = pk;
    }
}

// ---------------- T0 = x^T  ([B,N] -> [N,B]) + fp16 copy -----------------
__global__ void transpose_kernel(const float* __restrict__ x) {
    __shared__ float tile[32][33];
    int n0 = blockIdx.x * 32, b0 = blockIdx.y * 32;
    int tn = n0 + threadIdx.x;
    int tb = b0 + threadIdx.y;          // always < 128
    if (tn < NN) tile[threadIdx.y][threadIdx.x] = x[(size_t)tb * NN + tn];
    __syncthreads();
    int on = n0 + threadIdx.y;
    int ob = b0 + threadIdx.x;
    if (on < NN) {
        float f = tile[threadIdx.x][threadIdx.y];
        g_T[(size_t)on * BB + ob] = f;
        // fp16 copy into slot 0 (plane 0 has parity 0)
        __half* th = (__half*)g_Th;
        th[(size_t)on * BB + ob] = __float2half(f);
    }
}

// -------------------- fused Chebyshev SpMM step --------------------------
// T_out[n,:] = alpha * sum_e val_e * fp16(T_in)[col_e,:]  + beta * T_prev[n,:]
// warp per row; lane covers 4 batch elements (fp16 gather = uint2 = 8B/lane)
__device__ __forceinline__ void gacc(uint2 r, float v,
                                     float& ax, float& ay, float& az, float& aw) {
    __half2 h0 = *reinterpret_cast<__half2*>(&r.x);
    __half2 h1 = *reinterpret_cast<__half2*>(&r.y);
    float2 f0 = __half22float2(h0);
    float2 f1 = __half22float2(h1);
    ax = fmaf(v, f0.x, ax);
    ay = fmaf(v, f0.y, ay);
    az = fmaf(v, f1.x, az);
    aw = fmaf(v, f1.y, aw);
}

__global__ void __launch_bounds__(256) spmm_kernel(int kin2, int kout,
                                                   int slot_in, int slot_out,
                                                   float alpha, float beta) {
    int gw = (blockIdx.x * blockDim.x + threadIdx.x) >> 5;
    int lane = threadIdx.x & 31;
    if (gw >= NN) return;

    const uint2* __restrict__ Th = g_Th + (size_t)slot_in * NN * 32;
    float4* __restrict__ Tout = (float4*)(g_T + (size_t)kout * NB);

    int s = g_rowptr[gw];
    int e = g_rowptr[gw + 1];

    float ax = 0.f, ay = 0.f, az = 0.f, aw = 0.f;
    int j = s;
    for (; j + 8 <= e; j += 8) {
        int2 p0 = g_pack[j + 0], p1 = g_pack[j + 1], p2 = g_pack[j + 2], p3 = g_pack[j + 3];
        int2 p4 = g_pack[j + 4], p5 = g_pack[j + 5], p6 = g_pack[j + 6], p7 = g_pack[j + 7];
        uint2 r0 = Th[(size_t)p0.x * 32 + lane];
        uint2 r1 = Th[(size_t)p1.x * 32 + lane];
        uint2 r2 = Th[(size_t)p2.x * 32 + lane];
        uint2 r3 = Th[(size_t)p3.x * 32 + lane];
        uint2 r4 = Th[(size_t)p4.x * 32 + lane];
        uint2 r5 = Th[(size_t)p5.x * 32 + lane];
        uint2 r6 = Th[(size_t)p6.x * 32 + lane];
        uint2 r7 = Th[(size_t)p7.x * 32 + lane];
        gacc(r0, __int_as_float(p0.y), ax, ay, az, aw);
        gacc(r1, __int_as_float(p1.y), ax, ay, az, aw);
        gacc(r2, __int_as_float(p2.y), ax, ay, az, aw);
        gacc(r3, __int_as_float(p3.y), ax, ay, az, aw);
        gacc(r4, __int_as_float(p4.y), ax, ay, az, aw);
        gacc(r5, __int_as_float(p5.y), ax, ay, az, aw);
        gacc(r6, __int_as_float(p6.y), ax, ay, az, aw);
        gacc(r7, __int_as_float(p7.y), ax, ay, az, aw);
    }
    for (; j < e; j++) {
        int2 p = g_pack[j];
        uint2 r = Th[(size_t)p.x * 32 + lane];
        gacc(r, __int_as_float(p.y), ax, ay, az, aw);
    }

    float4 o;
    if (beta != 0.f) {
        const float4* __restrict__ Tp = (const float4*)(g_T + (size_t)kin2 * NB);
        float4 p = Tp[(size_t)gw * 32 + lane];
        o.x = fmaf(alpha, ax, beta * p.x);
        o.y = fmaf(alpha, ay, beta * p.y);
        o.z = fmaf(alpha, az, beta * p.z);
        o.w = fmaf(alpha, aw, beta * p.w);
    } else {
        o.x = ax; o.y = ay; o.z = az; o.w = aw;   // alpha == 1 for T1
    }
    Tout[(size_t)gw * 32 + lane] = o;

    if (slot_out >= 0) {
        uint2* __restrict__ ThO = g_Th + (size_t)slot_out * NN * 32;
        __half2 h01 = __floats2half2_rn(o.x, o.y);
        __half2 h23 = __floats2half2_rn(o.z, o.w);
        uint2 u;
        u.x = *reinterpret_cast<unsigned*>(&h01);
        u.y = *reinterpret_cast<unsigned*>(&h23);
        ThO[(size_t)gw * 32 + lane] = u;
    }
}

// --------- fused epilogue: gc einsum + relu + FC partial sums ------------
__global__ void __launch_bounds__(128) final_kernel(const float* __restrict__ Wgc,
                                                    const float* __restrict__ bgc,
                                                    const float* __restrict__ Wfc) {
    __shared__ float sW[KK * 12];   // padded to 12 floats/row for float4 LDS
    __shared__ float sb[10];
    int t = threadIdx.x;
    for (int i = t; i < KK * 12; i += 128) sW[i] = 0.f;
    __syncthreads();
    for (int i = t; i < KK * 10; i += 128) {
        int k = i / 10, f = i % 10;
        sW[k * 12 + f] = Wgc[i];
    }
    if (t < 10) sb[t] = bgc[t];
    __syncthreads();

    const float4* sW4 = (const float4*)sW;
    int b = t;

    float h[10];
#pragma unroll
    for (int j = 0; j < 10; j++) h[j] = 0.f;

    int n0 = blockIdx.x * CHUNK;
    for (int n = n0; n < n0 + CHUNK; n++) {
        float gc[10];
#pragma unroll
        for (int f = 0; f < 10; f++) gc[f] = sb[f];
#pragma unroll
        for (int k = 0; k < KK; k++) {
            float tk = g_T[(size_t)k * NB + (size_t)n * BB + b];
            float4 wA = sW4[k * 3 + 0];
            float4 wB = sW4[k * 3 + 1];
            float4 wC = sW4[k * 3 + 2];
            gc[0] += tk * wA.x; gc[1] += tk * wA.y; gc[2] += tk * wA.z; gc[3] += tk * wA.w;
            gc[4] += tk * wB.x; gc[5] += tk * wB.y; gc[6] += tk * wB.z; gc[7] += tk * wB.w;
            gc[8] += tk * wC.x; gc[9] += tk * wC.y;
        }
#pragma unroll
        for (int f = 0; f < 10; f++) gc[f] = fmaxf(gc[f], 0.f);

        const float4* __restrict__ w4 = (const float4*)(Wfc + (size_t)n * 100);
#pragma unroll
        for (int q = 0; q < 25; q++) {
            float4 wv = w4[q];
            h[(4 * q + 0) % 10] += gc[(4 * q + 0) / 10] * wv.x;
            h[(4 * q + 1) % 10] += gc[(4 * q + 1) / 10] * wv.y;
            h[(4 * q + 2) % 10] += gc[(4 * q + 2) / 10] * wv.z;
            h[(4 * q + 3) % 10] += gc[(4 * q + 3) / 10] * wv.w;
        }
    }

    float* out = g_partial + (size_t)blockIdx.x * BB * 10 + (size_t)b * 10;
#pragma unroll
    for (int j = 0; j < 10; j++) out[j] = h[j];
}

// ------------- deterministic chunk reduction + bias/relu/softmax ---------
__global__ void reduce_softmax_kernel(const float* __restrict__ bfc,
                                      float* __restrict__ out) {
    int b = threadIdx.x;   // 128 threads
    float h[10];
#pragma unroll
    for (int j = 0; j < 10; j++) h[j] = 0.f;
    for (int c = 0; c < NCHUNK; c++) {
        const float* p = g_partial + (size_t)c * BB * 10 + (size_t)b * 10;
#pragma unroll
        for (int j = 0; j < 10; j++) h[j] += p[j];
    }
#pragma unroll
    for (int j = 0; j < 10; j++) h[j] = fmaxf(h[j] + bfc[j], 0.f);
    float m = h[0];
#pragma unroll
    for (int j = 1; j < 10; j++) m = fmaxf(m, h[j]);
    float ex[10];
    float s = 0.f;
#pragma unroll
    for (int j = 0; j < 10; j++) { ex[j] = expf(h[j] - m); s += ex[j]; }
    float inv = 1.f / s;
#pragma unroll
    for (int j = 0; j < 10; j++) out[(size_t)b * 10 + j] = ex[j] * inv;
}

// ------------------------------- launch ----------------------------------
extern "C" void kernel_launch(void* const* d_in, const int* in_sizes, int n_in,
                              void* d_out, int out_size) {
    const float* x    = (const float*)d_in[0];
    const int*   rows = (const int*)d_in[1];
    const int*   cols = (const int*)d_in[2];
    const float* vals = (const float*)d_in[3];
    const float* Wgc  = (const float*)d_in[4];
    const float* bgc  = (const float*)d_in[5];
    const float* Wfc  = (const float*)d_in[6];
    const float* bfc  = (const float*)d_in[7];
    float* out = (float*)d_out;

    // CSR build (replayed per graph launch)
    zero_deg_kernel<<<(NN + 256) / 256, 256>>>();
    degree_kernel<<<(EE + 255) / 256, 256>>>(rows);
    scan_kernel<<<1, 1024>>>();
    scatter_kernel<<<(EE + 255) / 256, 256>>>(rows, cols, vals);

    // T0 = x^T (fp32 + fp16 slot 0)
    dim3 tb(32, 32), tg((NN + 31) / 32, (BB + 31) / 32);
    transpose_kernel<<<tg, tb>>>(x);

    // Chebyshev chain: T1 = L T0 ; T_k = 2 L T_{k-1} - T_{k-2}
    // fp16 gather slot parity = k & 1; last step writes no fp16 copy.
    const int SPMM_GRID = (NN * 32 + 255) / 256;   // warp per row
    spmm_kernel<<<SPMM_GRID, 256>>>(0, 1, 0, 1, 1.0f, 0.0f);
    for (int k = 2; k < KK; k++) {
        int slot_out = (k == KK - 1) ? -1 : (k & 1);
        spmm_kernel<<<SPMM_GRID, 256>>>(k - 2, k, (k - 1) & 1, slot_out, 2.0f, -1.0f);
    }

    // fused epilogue + deterministic reduce + softmax
    final_kernel<<<NCHUNK, 128>>>(Wgc, bgc, Wfc);
    reduce_softmax_kernel<<<1, 128>>>(bfc, out);
}